// round 9
// baseline (speedup 1.0000x reference)
#include <cuda_runtime.h>

#define NG     64
#define NN     2048
#define F      128
#define H      4
#define CHUNK  128
#define SPLIT  (NN/CHUNK)     // 16
#define NCHUNK (NG*SPLIT)     // 1024
#define TB     512
#define PST    132
#define GRID1  148

typedef unsigned long long u64;

__device__ float g_wa[H*F];
__device__ float g_part[NCHUNK*H*PST];
__device__ int   g_gcnt[NG];

__device__ __forceinline__ u64 ffma2(u64 a, u64 b, u64 c) {
    u64 d; asm("fma.rn.f32x2 %0,%1,%2,%3;" : "=l"(d) : "l"(a), "l"(b), "l"(c)); return d;
}
__device__ __forceinline__ u64 addf2(u64 a, u64 b) {
    u64 d; asm("add.rn.f32x2 %0,%1,%2;" : "=l"(d) : "l"(a), "l"(b)); return d;
}
__device__ __forceinline__ u64 dup2(float x) {
    u64 d; asm("mov.b64 %0,{%1,%1};" : "=l"(d) : "f"(x)); return d;
}
__device__ __forceinline__ float2 u2f(u64 v) {
    float2 r; asm("mov.b64 {%0,%1},%2;" : "=f"(r.x), "=f"(r.y) : "l"(v)); return r;
}
__device__ __forceinline__ unsigned smem_u32(const void* p) {
    unsigned a;
    asm("{ .reg .u64 t; cvta.to.shared.u64 t, %1; cvt.u32.u64 %0, t; }" : "=r"(a) : "l"(p));
    return a;
}

// smem layout (bytes): 3 ring buffers + scratch
#define SXB      65536      // one buffer: 128 rows x 32 float4, swizzled
#define SWA_OFF  196608     // wa[4][128]                         2048
#define PP_OFF   198656     // p[128][4]                          2048
#define DP_OFF   200704     // scratch 2048 floats                8192
#define RED_OFF  208896     // float red[16]                        64
#define BC_OFF   208960     // 4 ints                               16
#define SV_OFF   208976     // sinv[4]                              16
#define SMEM_SZ  208992

// ---------------------------------------------------------------------------
__global__ void __launch_bounds__(256) k0_wa(
        const float* __restrict__ W1, const float* __restrict__ a1,
        const float* __restrict__ W2, const float* __restrict__ a2,
        const float* __restrict__ W3, const float* __restrict__ a3,
        const float* __restrict__ W4, const float* __restrict__ a4) {
    const int bid = blockIdx.x, t = threadIdx.x;
    if (bid == H) {
        if (t < NG) g_gcnt[t] = 0;
        return;
    }
    const float* W = (bid == 0) ? W1 : (bid == 1) ? W2 : (bid == 2) ? W3 : W4;
    const float* A = (bid == 0) ? a1 : (bid == 1) ? a2 : (bid == 2) ? a3 : a4;
    const int lane = t & 31, w = t >> 5;
    float4 av = *reinterpret_cast<const float4*>(A + lane*4);
    #pragma unroll
    for (int o = 0; o < 16; o++) {
        int i = w*16 + o;
        float4 wv = *reinterpret_cast<const float4*>(W + i*F + lane*4);
        float d = wv.x*av.x + wv.y*av.y + wv.z*av.z + wv.w*av.w;
        #pragma unroll
        for (int off = 16; off; off >>= 1)
            d += __shfl_xor_sync(0xffffffffu, d, off);
        if (lane == 0) g_wa[bid*F + i] = d;
    }
}

// ---------------------------------------------------------------------------
// k1: persistent, static round-robin chunks (NO steal atomics), 3-deep ring
// ---------------------------------------------------------------------------
__global__ void __launch_bounds__(TB) k1_main(
        const float* __restrict__ feat,
        const float* __restrict__ W1, const float* __restrict__ W2,
        const float* __restrict__ W3, const float* __restrict__ W4,
        const float* __restrict__ Wo, float* __restrict__ out) {
    extern __shared__ char smem[];
    float*      s_wa  = (float*)(smem + SWA_OFF);
    ulonglong2* s_wa2 = (ulonglong2*)(smem + SWA_OFF);
    float*      s_ppf = (float*)(smem + PP_OFF);
    ulonglong2* s_pp2 = (ulonglong2*)(smem + PP_OFF);
    float*      s_dpf = (float*)(smem + DP_OFF);
    float4*     s_dp  = (float4*)(smem + DP_OFF);
    ulonglong2* s_vp2 = (ulonglong2*)(smem + DP_OFF);
    float*      s_red = (float*)(smem + RED_OFF);
    int*        s_bc  = (int*)(smem + BC_OFF);
    float*      s_sv  = (float*)(smem + SV_OFF);

    const int t = threadIdx.x, lane = t & 31, w = t >> 5;
    const int bid = blockIdx.x;
    const unsigned smb = smem_u32(smem);

    if (t < 512) s_wa[t] = g_wa[t];

    // prefetch chunk c into ring buffer b; ALWAYS commits a group (empty ok)
    auto prefetch = [&](int c, int b) {
        if (c < NCHUNK) {
            const char* src = (const char*)(feat + (size_t)c * CHUNK * F);
            unsigned base = smb + (unsigned)b * SXB;
            #pragma unroll
            for (int k = 0; k < 8; k++) {
                int q = t + k*TB;
                int row = q >> 5, c4 = q & 31;
                unsigned dst = base + (unsigned)((row*32 + (c4 ^ (row & 7))) * 16);
                asm volatile("cp.async.cg.shared.global [%0],[%1],16;"
                             :: "r"(dst), "l"(src + (size_t)q*16));
            }
        }
        asm volatile("cp.async.commit_group;");
    };

    // static schedule: chunks bid, bid+148, bid+296, ...
    int cur = bid;
    int nx  = bid + GRID1;
    prefetch(cur, 0);
    prefetch(nx, 1);

    int buf = 0;
    while (cur < NCHUNK) {
        const int b2 = (buf == 0) ? 2 : (buf == 1) ? 0 : 1;
        const int c2 = nx + GRID1;
        prefetch(c2, b2);                        // commit (empty if OOB)
        asm volatile("cp.async.wait_group 2;");  // cur's copy complete
        __syncthreads();

        float*      s_sxf = (float*)(smem + (unsigned)buf * SXB);
        ulonglong2* s_sx2 = (ulonglong2*)s_sxf;
        const int grp = cur >> 4;
        float* pb = g_part + (size_t)cur * H * PST;

        // ---- P1: 4 threads per row (quarter-columns), f32x2 dots ----------
        {
            const int row = t & 127, q = t >> 7, r7 = row & 7;
            u64 d2[H] = {0ull, 0ull, 0ull, 0ull};
            #pragma unroll
            for (int jj = 0; jj < 8; jj++) {
                int j = q*8 + jj;
                ulonglong2 f = s_sx2[row*32 + (j ^ r7)];
                #pragma unroll
                for (int h = 0; h < H; h++) {
                    ulonglong2 wv = s_wa2[h*32 + j];
                    d2[h] = ffma2(f.x, wv.x, d2[h]);
                    d2[h] = ffma2(f.y, wv.y, d2[h]);
                }
            }
            float2 a0 = u2f(d2[0]), a1 = u2f(d2[1]), a2 = u2f(d2[2]), a3 = u2f(d2[3]);
            s_dp[t] = make_float4(a0.x+a0.y, a1.x+a1.y, a2.x+a2.y, a3.x+a3.y);
        }
        __syncthreads();

        // ---- combine quarters, exp (1 per (row,head)), warp s-sums --------
        {
            const int row = t & 127, h = t >> 7;
            float d = s_dpf[row*4 + h] + s_dpf[(row+128)*4 + h]
                    + s_dpf[(row+256)*4 + h] + s_dpf[(row+384)*4 + h];
            float pv = __expf(d);
            s_ppf[row*4 + h] = pv;
            float sv = pv;
            #pragma unroll
            for (int off = 16; off; off >>= 1)
                sv += __shfl_xor_sync(0xffffffffu, sv, off);
            if (lane == 0) s_red[w] = sv;   // warp w: head w>>2
        }
        __syncthreads();

        if (t < H)
            pb[t*PST + F] = s_red[4*t] + s_red[4*t+1] + s_red[4*t+2] + s_red[4*t+3];

        // ---- P2: 4 threads per column (32 rows each), f32x2 over heads ----
        {
            const int col = t & 127, rq = t >> 7;
            const int cq = col >> 2, cl = col & 3;
            const int r0 = rq * 32;
            u64 a01a = 0ull, a23a = 0ull, a01b = 0ull, a23b = 0ull;
            #pragma unroll 8
            for (int r = 0; r < 32; r += 2) {
                int ra = r0 + r, rb = ra + 1;
                ulonglong2 pa  = s_pp2[ra];
                ulonglong2 pbv = s_pp2[rb];
                u64 xa = dup2(s_sxf[ra*F + ((cq ^ (ra & 7)) << 2) + cl]);
                u64 xb = dup2(s_sxf[rb*F + ((cq ^ (rb & 7)) << 2) + cl]);
                a01a = ffma2(pa.x,  xa, a01a);
                a23a = ffma2(pa.y,  xa, a23a);
                a01b = ffma2(pbv.x, xb, a01b);
                a23b = ffma2(pbv.y, xb, a23b);
            }
            __syncthreads();          // all s_dp reads done before overwrite
            ulonglong2 vr;
            vr.x = addf2(a01a, a01b);
            vr.y = addf2(a23a, a23b);
            s_vp2[t] = vr;
        }
        __syncthreads();

        if (t < 128) {
            ulonglong2 A = s_vp2[t], B = s_vp2[t+128];
            ulonglong2 C = s_vp2[t+256], D = s_vp2[t+384];
            float2 v01 = u2f(addf2(addf2(A.x, B.x), addf2(C.x, D.x)));
            float2 v23 = u2f(addf2(addf2(A.y, B.y), addf2(C.y, D.y)));
            pb[0*PST + t] = v01.x;
            pb[1*PST + t] = v01.y;
            pb[2*PST + t] = v23.x;
            pb[3*PST + t] = v23.y;
        }

        // ---- completion; last chunk of group runs epilogue ----------------
        __threadfence();
        __syncthreads();
        if (t == 0) {
            int old = atomicAdd(&g_gcnt[grp], 1);
            s_bc[3] = (old == SPLIT - 1);
        }
        __syncthreads();
        if (s_bc[3]) {
            __threadfence();
            float* pooled = s_dpf;           // [512]
            float* multi  = s_dpf + 512;     // [512]
            float* red8   = s_dpf + 1024;    // [512]
            const float* pg = g_part + (size_t)grp * SPLIT * H * PST;
            if (t < H) {
                float ss = 0.f;
                #pragma unroll
                for (int cc = 0; cc < SPLIT; cc++) ss += pg[(cc*H + t)*PST + F];
                s_sv[t] = 1.0f / ss;
            }
            __syncthreads();
            {
                int h = t >> 7, i = t & 127;
                float vv = 0.f;
                #pragma unroll
                for (int cc = 0; cc < SPLIT; cc++) vv += pg[(cc*H + h)*PST + i];
                pooled[t] = vv * s_sv[h];
            }
            __syncthreads();
            {
                int h = t >> 7, j = t & 127;
                const float* Wp = (h == 0) ? W1 : (h == 1) ? W2 : (h == 2) ? W3 : W4;
                float acc = 0.f;
                #pragma unroll 8
                for (int i = 0; i < F; i++)
                    acc = fmaf(pooled[h*F + i], Wp[i*F + j], acc);
                multi[t] = acc;
            }
            __syncthreads();
            {
                int oc = t & 63, seg = t >> 6;   // 8 segments of 64 k
                float acc = 0.f;
                #pragma unroll 8
                for (int kk = 0; kk < 64; kk++) {
                    int k = seg*64 + kk;
                    acc = fmaf(multi[k], Wo[k*64 + oc], acc);
                }
                red8[seg*64 + oc] = acc;
            }
            __syncthreads();
            if (t < 64) {
                float a = 0.f;
                #pragma unroll
                for (int sgg = 0; sgg < 8; sgg++) a += red8[sgg*64 + t];
                out[grp*64 + t] = (a > 0.f) ? a : expm1f(a);
            }
            __syncthreads();   // keep epilogue smem safe vs next-iter scratch use
        }

        cur = nx; nx = c2; buf = (buf == 2) ? 0 : buf + 1;
    }
    asm volatile("cp.async.wait_group 0;");
}

// ---------------------------------------------------------------------------
extern "C" void kernel_launch(void* const* d_in, const int* in_sizes, int n_in,
                              void* d_out, int out_size) {
    const float* feat = (const float*)d_in[0];
    const float* W1   = (const float*)d_in[1];
    const float* a1   = (const float*)d_in[2];
    const float* W2   = (const float*)d_in[3];
    const float* a2   = (const float*)d_in[4];
    const float* W3   = (const float*)d_in[5];
    const float* a3   = (const float*)d_in[6];
    const float* W4   = (const float*)d_in[7];
    const float* a4   = (const float*)d_in[8];
    const float* Wo   = (const float*)d_in[9];
    float* out = (float*)d_out;

    cudaFuncSetAttribute(k1_main, cudaFuncAttributeMaxDynamicSharedMemorySize, SMEM_SZ);
    k0_wa<<<H + 1, 256>>>(W1, a1, W2, a2, W3, a3, W4, a4);
    k1_main<<<GRID1, TB, SMEM_SZ>>>(feat, W1, W2, W3, W4, Wo, out);
}

// round 10
// speedup vs baseline: 1.3730x; 1.3730x over previous
#include <cuda_runtime.h>

#define NG     64
#define NN     2048
#define F      128
#define H      4
#define CHUNK  128
#define SPLIT  (NN/CHUNK)     // 16
#define NCHUNK (NG*SPLIT)     // 1024
#define TB     512
#define PST    132
#define GRID1  148

typedef unsigned long long u64;

__device__ float g_wa[H*F];
__device__ float g_part[NCHUNK*H*PST];
__device__ int   g_work;
__device__ int   g_gcnt[NG];

__device__ __forceinline__ u64 ffma2(u64 a, u64 b, u64 c) {
    u64 d; asm("fma.rn.f32x2 %0,%1,%2,%3;" : "=l"(d) : "l"(a), "l"(b), "l"(c)); return d;
}
__device__ __forceinline__ u64 addf2(u64 a, u64 b) {
    u64 d; asm("add.rn.f32x2 %0,%1,%2;" : "=l"(d) : "l"(a), "l"(b)); return d;
}
__device__ __forceinline__ u64 dup2(float x) {
    u64 d; asm("mov.b64 %0,{%1,%1};" : "=l"(d) : "f"(x)); return d;
}
__device__ __forceinline__ float2 u2f(u64 v) {
    float2 r; asm("mov.b64 {%0,%1},%2;" : "=f"(r.x), "=f"(r.y) : "l"(v)); return r;
}
__device__ __forceinline__ unsigned smem_u32(const void* p) {
    unsigned a;
    asm("{ .reg .u64 t; cvta.to.shared.u64 t, %1; cvt.u32.u64 %0, t; }" : "=r"(a) : "l"(p));
    return a;
}

// smem layout (bytes): 3 ring buffers + scratch
#define SXB      65536      // one buffer: 128 rows x 32 float4, swizzled
#define SWA_OFF  196608     // wa[4][128]                         2048
#define PP_OFF   198656     // p[128][4]                          2048
#define DP_OFF   200704     // scratch 2048 floats                8192
#define RED_OFF  208896     // float red[16]                        64
#define BC_OFF   208960     // 4 ints                               16
#define SV_OFF   208976     // sinv[4]                              16
#define SMEM_SZ  208992

// ---------------------------------------------------------------------------
__global__ void __launch_bounds__(256) k0_wa(
        const float* __restrict__ W1, const float* __restrict__ a1,
        const float* __restrict__ W2, const float* __restrict__ a2,
        const float* __restrict__ W3, const float* __restrict__ a3,
        const float* __restrict__ W4, const float* __restrict__ a4) {
    const int bid = blockIdx.x, t = threadIdx.x;
    if (bid == H) {
        if (t < NG) g_gcnt[t] = 0;
        if (t == NG) g_work = 0;
        return;
    }
    const float* W = (bid == 0) ? W1 : (bid == 1) ? W2 : (bid == 2) ? W3 : W4;
    const float* A = (bid == 0) ? a1 : (bid == 1) ? a2 : (bid == 2) ? a3 : a4;
    const int lane = t & 31, w = t >> 5;
    float4 av = *reinterpret_cast<const float4*>(A + lane*4);
    #pragma unroll
    for (int o = 0; o < 16; o++) {
        int i = w*16 + o;
        float4 wv = *reinterpret_cast<const float4*>(W + i*F + lane*4);
        float d = wv.x*av.x + wv.y*av.y + wv.z*av.z + wv.w*av.w;
        #pragma unroll
        for (int off = 16; off; off >>= 1)
            d += __shfl_xor_sync(0xffffffffu, d, off);
        if (lane == 0) g_wa[bid*F + i] = d;
    }
}

// ---------------------------------------------------------------------------
// k1: persistent, work-stealing, 3-deep cp.async ring + L2 prefetch stream
// ---------------------------------------------------------------------------
__global__ void __launch_bounds__(TB) k1_main(
        const float* __restrict__ feat,
        const float* __restrict__ W1, const float* __restrict__ W2,
        const float* __restrict__ W3, const float* __restrict__ W4,
        const float* __restrict__ Wo, float* __restrict__ out) {
    extern __shared__ char smem[];
    float*      s_wa  = (float*)(smem + SWA_OFF);
    ulonglong2* s_wa2 = (ulonglong2*)(smem + SWA_OFF);
    float*      s_ppf = (float*)(smem + PP_OFF);
    ulonglong2* s_pp2 = (ulonglong2*)(smem + PP_OFF);
    float*      s_dpf = (float*)(smem + DP_OFF);
    float4*     s_dp  = (float4*)(smem + DP_OFF);
    ulonglong2* s_vp2 = (ulonglong2*)(smem + DP_OFF);
    float*      s_red = (float*)(smem + RED_OFF);
    int*        s_bc  = (int*)(smem + BC_OFF);
    float*      s_sv  = (float*)(smem + SV_OFF);

    const int t = threadIdx.x, lane = t & 31, w = t >> 5;
    const int bid = blockIdx.x;
    const unsigned smb = smem_u32(smem);

    if (t < 512) s_wa[t] = g_wa[t];

    // L2 prefetch of one 64KB chunk: 512 threads x 1 cache line
    auto pf_l2 = [&](int c) {
        if (c < NCHUNK) {
            const char* p = (const char*)(feat + (size_t)c * CHUNK * F)
                            + (size_t)t * 128;
            asm volatile("prefetch.global.L2 [%0];" :: "l"(p));
        }
    };

    // demand stage of chunk c into ring buffer b; ALWAYS commits (empty ok)
    auto prefetch = [&](int c, int b) {
        if (c < NCHUNK) {
            const char* src = (const char*)(feat + (size_t)c * CHUNK * F);
            unsigned base = smb + (unsigned)b * SXB;
            #pragma unroll
            for (int k = 0; k < 8; k++) {
                int q = t + k*TB;
                int row = q >> 5, c4 = q & 31;
                unsigned dst = base + (unsigned)((row*32 + (c4 ^ (row & 7))) * 16);
                asm volatile("cp.async.cg.shared.global [%0],[%1],16;"
                             :: "r"(dst), "l"(src + (size_t)q*16));
            }
        }
        asm volatile("cp.async.commit_group;");
    };

    // static-coverage L2 prefetch: CTA bid covers chunks bid + k*GRID1
    int pfk = 0;
    pf_l2(bid);               pfk++;
    pf_l2(bid + GRID1);       pfk++;
    pf_l2(bid + 2*GRID1);     pfk++;

    // prime: steal 2, demand-stage into buffers 0,1
    if (t == 0) s_bc[0] = atomicAdd(&g_work, 1);
    __syncthreads();
    int cur = s_bc[0];
    prefetch(cur, 0);
    if (t == 0) s_bc[1] = atomicAdd(&g_work, 1);
    __syncthreads();
    int nx = s_bc[1];
    prefetch(nx, 1);

    int buf = 0;
    while (cur < NCHUNK) {
        // advance the L2 prefetch stream (2 chunks per iteration)
        pf_l2(bid + pfk*GRID1);       pfk++;
        pf_l2(bid + pfk*GRID1);       pfk++;

        // steal 2-ahead, demand-stage into buffer (buf+2)%3
        const int b2 = (buf == 0) ? 2 : (buf == 1) ? 0 : 1;
        if (t == 0) s_bc[b2] = atomicAdd(&g_work, 1);
        __syncthreads();                       // also: prev compute fully done
        const int c2 = s_bc[b2];
        prefetch(c2, b2);
        asm volatile("cp.async.wait_group 2;");  // cur's copy complete
        __syncthreads();

        float*      s_sxf = (float*)(smem + (unsigned)buf * SXB);
        ulonglong2* s_sx2 = (ulonglong2*)s_sxf;
        const int grp = cur >> 4;
        float* pb = g_part + (size_t)cur * H * PST;

        // ---- P1: 4 threads per row (quarter-columns), f32x2 dots ----------
        {
            const int row = t & 127, q = t >> 7, r7 = row & 7;
            u64 d2[H] = {0ull, 0ull, 0ull, 0ull};
            #pragma unroll
            for (int jj = 0; jj < 8; jj++) {
                int j = q*8 + jj;
                ulonglong2 f = s_sx2[row*32 + (j ^ r7)];
                #pragma unroll
                for (int h = 0; h < H; h++) {
                    ulonglong2 wv = s_wa2[h*32 + j];
                    d2[h] = ffma2(f.x, wv.x, d2[h]);
                    d2[h] = ffma2(f.y, wv.y, d2[h]);
                }
            }
            float2 a0 = u2f(d2[0]), a1 = u2f(d2[1]), a2 = u2f(d2[2]), a3 = u2f(d2[3]);
            s_dp[t] = make_float4(a0.x+a0.y, a1.x+a1.y, a2.x+a2.y, a3.x+a3.y);
        }
        __syncthreads();

        // ---- combine quarters, exp (1 per (row,head)), warp s-sums --------
        {
            const int row = t & 127, h = t >> 7;
            float d = s_dpf[row*4 + h] + s_dpf[(row+128)*4 + h]
                    + s_dpf[(row+256)*4 + h] + s_dpf[(row+384)*4 + h];
            float pv = __expf(d);
            s_ppf[row*4 + h] = pv;
            float sv = pv;
            #pragma unroll
            for (int off = 16; off; off >>= 1)
                sv += __shfl_xor_sync(0xffffffffu, sv, off);
            if (lane == 0) s_red[w] = sv;   // warp w: head w>>2
        }
        __syncthreads();

        if (t < H)
            pb[t*PST + F] = s_red[4*t] + s_red[4*t+1] + s_red[4*t+2] + s_red[4*t+3];

        // ---- P2: 4 threads per column (32 rows each), f32x2 over heads ----
        {
            const int col = t & 127, rq = t >> 7;
            const int cq = col >> 2, cl = col & 3;
            const int r0 = rq * 32;
            u64 a01a = 0ull, a23a = 0ull, a01b = 0ull, a23b = 0ull;
            #pragma unroll 8
            for (int r = 0; r < 32; r += 2) {
                int ra = r0 + r, rb = ra + 1;
                ulonglong2 pa  = s_pp2[ra];
                ulonglong2 pbv = s_pp2[rb];
                u64 xa = dup2(s_sxf[ra*F + ((cq ^ (ra & 7)) << 2) + cl]);
                u64 xb = dup2(s_sxf[rb*F + ((cq ^ (rb & 7)) << 2) + cl]);
                a01a = ffma2(pa.x,  xa, a01a);
                a23a = ffma2(pa.y,  xa, a23a);
                a01b = ffma2(pbv.x, xb, a01b);
                a23b = ffma2(pbv.y, xb, a23b);
            }
            __syncthreads();          // all s_dp reads done before overwrite
            ulonglong2 vr;
            vr.x = addf2(a01a, a01b);
            vr.y = addf2(a23a, a23b);
            s_vp2[t] = vr;
        }
        __syncthreads();

        if (t < 128) {
            ulonglong2 A = s_vp2[t], B = s_vp2[t+128];
            ulonglong2 C = s_vp2[t+256], D = s_vp2[t+384];
            float2 v01 = u2f(addf2(addf2(A.x, B.x), addf2(C.x, D.x)));
            float2 v23 = u2f(addf2(addf2(A.y, B.y), addf2(C.y, D.y)));
            pb[0*PST + t] = v01.x;
            pb[1*PST + t] = v01.y;
            pb[2*PST + t] = v23.x;
            pb[3*PST + t] = v23.y;
        }

        // ---- completion; last chunk of group runs epilogue ----------------
        __threadfence();
        __syncthreads();
        if (t == 0) {
            int old = atomicAdd(&g_gcnt[grp], 1);
            s_bc[3] = (old == SPLIT - 1);
        }
        __syncthreads();
        if (s_bc[3]) {
            __threadfence();
            float* pooled = s_dpf;           // [512]
            float* multi  = s_dpf + 512;     // [512]
            float* red8   = s_dpf + 1024;    // [512]
            const float* pg = g_part + (size_t)grp * SPLIT * H * PST;
            if (t < H) {
                float ss = 0.f;
                #pragma unroll
                for (int cc = 0; cc < SPLIT; cc++) ss += pg[(cc*H + t)*PST + F];
                s_sv[t] = 1.0f / ss;
            }
            __syncthreads();
            {
                int h = t >> 7, i = t & 127;
                float vv = 0.f;
                #pragma unroll
                for (int cc = 0; cc < SPLIT; cc++) vv += pg[(cc*H + h)*PST + i];
                pooled[t] = vv * s_sv[h];
            }
            __syncthreads();
            {
                int h = t >> 7, j = t & 127;
                const float* Wp = (h == 0) ? W1 : (h == 1) ? W2 : (h == 2) ? W3 : W4;
                float acc = 0.f;
                #pragma unroll 8
                for (int i = 0; i < F; i++)
                    acc = fmaf(pooled[h*F + i], Wp[i*F + j], acc);
                multi[t] = acc;
            }
            __syncthreads();
            {
                int oc = t & 63, seg = t >> 6;   // 8 segments of 64 k
                float acc = 0.f;
                #pragma unroll 8
                for (int kk = 0; kk < 64; kk++) {
                    int k = seg*64 + kk;
                    acc = fmaf(multi[k], Wo[k*64 + oc], acc);
                }
                red8[seg*64 + oc] = acc;
            }
            __syncthreads();
            if (t < 64) {
                float a = 0.f;
                #pragma unroll
                for (int sgg = 0; sgg < 8; sgg++) a += red8[sgg*64 + t];
                out[grp*64 + t] = (a > 0.f) ? a : expm1f(a);
            }
            __syncthreads();
        }

        cur = nx; nx = c2; buf = (buf == 2) ? 0 : buf + 1;
    }
    asm volatile("cp.async.wait_group 0;");
}

// ---------------------------------------------------------------------------
extern "C" void kernel_launch(void* const* d_in, const int* in_sizes, int n_in,
                              void* d_out, int out_size) {
    const float* feat = (const float*)d_in[0];
    const float* W1   = (const float*)d_in[1];
    const float* a1   = (const float*)d_in[2];
    const float* W2   = (const float*)d_in[3];
    const float* a2   = (const float*)d_in[4];
    const float* W3   = (const float*)d_in[5];
    const float* a3   = (const float*)d_in[6];
    const float* W4   = (const float*)d_in[7];
    const float* a4   = (const float*)d_in[8];
    const float* Wo   = (const float*)d_in[9];
    float* out = (float*)d_out;

    cudaFuncSetAttribute(k1_main, cudaFuncAttributeMaxDynamicSharedMemorySize, SMEM_SZ);
    k0_wa<<<H + 1, 256>>>(W1, a1, W2, a2, W3, a3, W4, a4);
    k1_main<<<GRID1, TB, SMEM_SZ>>>(feat, W1, W2, W3, W4, Wo, out);
}

// round 11
// speedup vs baseline: 1.3866x; 1.0099x over previous
#include <cuda_runtime.h>

#define NG     64
#define NN     2048
#define F      128
#define H      4
#define CHUNK  128
#define SPLIT  (NN/CHUNK)     // 16
#define NCHUNK (NG*SPLIT)     // 1024
#define TB     512
#define PST    132
#define GRID1  148

typedef unsigned long long u64;

__device__ float g_wa[H*F];
__device__ float g_part[NCHUNK*H*PST];
__device__ int   g_work;
__device__ int   g_gcnt[NG];

__device__ __forceinline__ u64 ffma2(u64 a, u64 b, u64 c) {
    u64 d; asm("fma.rn.f32x2 %0,%1,%2,%3;" : "=l"(d) : "l"(a), "l"(b), "l"(c)); return d;
}
__device__ __forceinline__ u64 addf2(u64 a, u64 b) {
    u64 d; asm("add.rn.f32x2 %0,%1,%2;" : "=l"(d) : "l"(a), "l"(b)); return d;
}
__device__ __forceinline__ u64 dup2(float x) {
    u64 d; asm("mov.b64 %0,{%1,%1};" : "=l"(d) : "f"(x)); return d;
}
__device__ __forceinline__ float2 u2f(u64 v) {
    float2 r; asm("mov.b64 {%0,%1},%2;" : "=f"(r.x), "=f"(r.y) : "l"(v)); return r;
}
__device__ __forceinline__ unsigned smem_u32(const void* p) {
    unsigned a;
    asm("{ .reg .u64 t; cvta.to.shared.u64 t, %1; cvt.u32.u64 %0, t; }" : "=r"(a) : "l"(p));
    return a;
}
__device__ __forceinline__ void mbar_wait(unsigned mbar, unsigned parity) {
    asm volatile(
        "{\n\t"
        ".reg .pred P1;\n\t"
        "WAIT_LOOP_%=:\n\t"
        "mbarrier.try_wait.parity.acquire.cta.shared::cta.b64 P1, [%0], %1, 0x989680;\n\t"
        "@P1 bra.uni WAIT_DONE_%=;\n\t"
        "bra.uni WAIT_LOOP_%=;\n\t"
        "WAIT_DONE_%=:\n\t"
        "}"
        :: "r"(mbar), "r"(parity) : "memory");
}

// smem layout (bytes): 3 ring buffers + scratch + mbarriers
#define SXB      65536      // one buffer: 128 rows x 32 float4 (linear from TMA)
#define SWA_OFF  196608     // wa[4][128]                         2048
#define PP_OFF   198656     // p[128][4]                          2048
#define DP_OFF   200704     // scratch 2048 floats                8192
#define RED_OFF  208896     // float red[16]                        64
#define BC_OFF   208960     // 4 ints                               16
#define SV_OFF   208976     // sinv[4]                              16
#define MBAR_OFF 208992     // 3 x 8B mbarriers                     24
#define SMEM_SZ  209024

// ---------------------------------------------------------------------------
__global__ void __launch_bounds__(256) k0_wa(
        const float* __restrict__ W1, const float* __restrict__ a1,
        const float* __restrict__ W2, const float* __restrict__ a2,
        const float* __restrict__ W3, const float* __restrict__ a3,
        const float* __restrict__ W4, const float* __restrict__ a4) {
    const int bid = blockIdx.x, t = threadIdx.x;
    if (bid == H) {
        if (t < NG) g_gcnt[t] = 0;
        if (t == NG) g_work = 0;
        return;
    }
    const float* W = (bid == 0) ? W1 : (bid == 1) ? W2 : (bid == 2) ? W3 : W4;
    const float* A = (bid == 0) ? a1 : (bid == 1) ? a2 : (bid == 2) ? a3 : a4;
    const int lane = t & 31, w = t >> 5;
    float4 av = *reinterpret_cast<const float4*>(A + lane*4);
    #pragma unroll
    for (int o = 0; o < 16; o++) {
        int i = w*16 + o;
        float4 wv = *reinterpret_cast<const float4*>(W + i*F + lane*4);
        float d = wv.x*av.x + wv.y*av.y + wv.z*av.z + wv.w*av.w;
        #pragma unroll
        for (int off = 16; off; off >>= 1)
            d += __shfl_xor_sync(0xffffffffu, d, off);
        if (lane == 0) g_wa[bid*F + i] = d;
    }
}

// ---------------------------------------------------------------------------
// k1: persistent, work-stealing, TMA-bulk ring of 3 + in-place swizzle pass
// ---------------------------------------------------------------------------
__global__ void __launch_bounds__(TB) k1_main(
        const float* __restrict__ feat,
        const float* __restrict__ W1, const float* __restrict__ W2,
        const float* __restrict__ W3, const float* __restrict__ W4,
        const float* __restrict__ Wo, float* __restrict__ out) {
    extern __shared__ char smem[];
    float*      s_wa  = (float*)(smem + SWA_OFF);
    ulonglong2* s_wa2 = (ulonglong2*)(smem + SWA_OFF);
    float*      s_ppf = (float*)(smem + PP_OFF);
    ulonglong2* s_pp2 = (ulonglong2*)(smem + PP_OFF);
    float*      s_dpf = (float*)(smem + DP_OFF);
    float4*     s_dp  = (float4*)(smem + DP_OFF);
    ulonglong2* s_vp2 = (ulonglong2*)(smem + DP_OFF);
    float*      s_red = (float*)(smem + RED_OFF);
    int*        s_bc  = (int*)(smem + BC_OFF);
    float*      s_sv  = (float*)(smem + SV_OFF);

    const int t = threadIdx.x, lane = t & 31, w = t >> 5;
    const unsigned smb = smem_u32(smem);
    const unsigned mb0 = smb + MBAR_OFF;

    if (t < 512) s_wa[t] = g_wa[t];

    // init 3 mbarriers (arrive count = 1: the expect_tx arrival)
    if (t == 0) {
        #pragma unroll
        for (int b = 0; b < 3; b++)
            asm volatile("mbarrier.init.shared.b64 [%0], %1;"
                         :: "r"(mb0 + b*8), "r"(1u) : "memory");
    }
    __syncthreads();

    // issue one 64KB TMA bulk copy of chunk c into buffer b (thread 0 only)
    auto issue = [&](int c, int b) {
        if (t == 0 && c < NCHUNK) {
            unsigned mb = mb0 + b*8;
            unsigned dst = smb + (unsigned)b * SXB;
            const char* src = (const char*)(feat + (size_t)c * CHUNK * F);
            asm volatile("fence.proxy.async.shared::cta;" ::: "memory");
            asm volatile("mbarrier.arrive.expect_tx.shared.b64 _, [%0], %1;"
                         :: "r"(mb), "r"((unsigned)SXB) : "memory");
            asm volatile(
                "cp.async.bulk.shared::cluster.global.mbarrier::complete_tx::bytes "
                "[%0], [%1], %2, [%3];"
                :: "r"(dst), "l"(src), "r"((unsigned)SXB), "r"(mb) : "memory");
        }
    };

    // prime: steal 2 chunks into buffers 0,1
    if (t == 0) s_bc[0] = atomicAdd(&g_work, 1);
    __syncthreads();
    int cur = s_bc[0];
    issue(cur, 0);
    if (t == 0) s_bc[1] = atomicAdd(&g_work, 1);
    __syncthreads();
    int nx = s_bc[1];
    issue(nx, 1);

    unsigned phases = 0;   // parity bit per mbarrier
    int buf = 0;
    while (cur < NCHUNK) {
        // steal 2-ahead, TMA into buffer (buf+2)%3
        const int b2 = (buf == 0) ? 2 : (buf == 1) ? 0 : 1;
        if (t == 0) s_bc[2] = atomicAdd(&g_work, 1);
        __syncthreads();                       // prev compute done; s_bc visible
        const int c2 = s_bc[2];
        issue(c2, b2);

        // wait for cur's bulk copy
        mbar_wait(mb0 + buf*8, (phases >> buf) & 1u);
        phases ^= (1u << buf);

        float*      s_sxf = (float*)(smem + (unsigned)buf * SXB);
        float4*     s_sb4 = (float4*)s_sxf;
        ulonglong2* s_sx2 = (ulonglong2*)s_sxf;

        // ---- in-place XOR swizzle (warp w owns rows 8w..8w+7) -------------
        {
            const int r0 = w * 8;
            #pragma unroll
            for (int half = 0; half < 2; half++) {
                float4 v0 = s_sb4[(r0 + half*4 + 0)*32 + lane];
                float4 v1 = s_sb4[(r0 + half*4 + 1)*32 + lane];
                float4 v2 = s_sb4[(r0 + half*4 + 2)*32 + lane];
                float4 v3 = s_sb4[(r0 + half*4 + 3)*32 + lane];
                __syncwarp();
                s_sb4[(r0 + half*4 + 0)*32 + (lane ^ ((r0 + half*4 + 0) & 7))] = v0;
                s_sb4[(r0 + half*4 + 1)*32 + (lane ^ ((r0 + half*4 + 1) & 7))] = v1;
                s_sb4[(r0 + half*4 + 2)*32 + (lane ^ ((r0 + half*4 + 2) & 7))] = v2;
                s_sb4[(r0 + half*4 + 3)*32 + (lane ^ ((r0 + half*4 + 3) & 7))] = v3;
                __syncwarp();
            }
        }
        __syncthreads();

        const int grp = cur >> 4;
        float* pb = g_part + (size_t)cur * H * PST;

        // ---- P1: 4 threads per row (quarter-columns), f32x2 dots ----------
        {
            const int row = t & 127, q = t >> 7, r7 = row & 7;
            u64 d2[H] = {0ull, 0ull, 0ull, 0ull};
            #pragma unroll
            for (int jj = 0; jj < 8; jj++) {
                int j = q*8 + jj;
                ulonglong2 f = s_sx2[row*32 + (j ^ r7)];
                #pragma unroll
                for (int h = 0; h < H; h++) {
                    ulonglong2 wv = s_wa2[h*32 + j];
                    d2[h] = ffma2(f.x, wv.x, d2[h]);
                    d2[h] = ffma2(f.y, wv.y, d2[h]);
                }
            }
            float2 a0 = u2f(d2[0]), a1 = u2f(d2[1]), a2 = u2f(d2[2]), a3 = u2f(d2[3]);
            s_dp[t] = make_float4(a0.x+a0.y, a1.x+a1.y, a2.x+a2.y, a3.x+a3.y);
        }
        __syncthreads();

        // ---- combine quarters, exp (1 per (row,head)), warp s-sums --------
        {
            const int row = t & 127, h = t >> 7;
            float d = s_dpf[row*4 + h] + s_dpf[(row+128)*4 + h]
                    + s_dpf[(row+256)*4 + h] + s_dpf[(row+384)*4 + h];
            float pv = __expf(d);
            s_ppf[row*4 + h] = pv;
            float sv = pv;
            #pragma unroll
            for (int off = 16; off; off >>= 1)
                sv += __shfl_xor_sync(0xffffffffu, sv, off);
            if (lane == 0) s_red[w] = sv;   // warp w: head w>>2
        }
        __syncthreads();

        if (t < H)
            pb[t*PST + F] = s_red[4*t] + s_red[4*t+1] + s_red[4*t+2] + s_red[4*t+3];

        // ---- P2: 4 threads per column (32 rows each), f32x2 over heads ----
        {
            const int col = t & 127, rq = t >> 7;
            const int cq = col >> 2, cl = col & 3;
            const int r0 = rq * 32;
            u64 a01a = 0ull, a23a = 0ull, a01b = 0ull, a23b = 0ull;
            #pragma unroll 8
            for (int r = 0; r < 32; r += 2) {
                int ra = r0 + r, rb = ra + 1;
                ulonglong2 pa  = s_pp2[ra];
                ulonglong2 pbv = s_pp2[rb];
                u64 xa = dup2(s_sxf[ra*F + ((cq ^ (ra & 7)) << 2) + cl]);
                u64 xb = dup2(s_sxf[rb*F + ((cq ^ (rb & 7)) << 2) + cl]);
                a01a = ffma2(pa.x,  xa, a01a);
                a23a = ffma2(pa.y,  xa, a23a);
                a01b = ffma2(pbv.x, xb, a01b);
                a23b = ffma2(pbv.y, xb, a23b);
            }
            __syncthreads();          // all s_dp reads done before overwrite
            ulonglong2 vr;
            vr.x = addf2(a01a, a01b);
            vr.y = addf2(a23a, a23b);
            s_vp2[t] = vr;
        }
        __syncthreads();

        if (t < 128) {
            ulonglong2 A = s_vp2[t], B = s_vp2[t+128];
            ulonglong2 C = s_vp2[t+256], D = s_vp2[t+384];
            float2 v01 = u2f(addf2(addf2(A.x, B.x), addf2(C.x, D.x)));
            float2 v23 = u2f(addf2(addf2(A.y, B.y), addf2(C.y, D.y)));
            pb[0*PST + t] = v01.x;
            pb[1*PST + t] = v01.y;
            pb[2*PST + t] = v23.x;
            pb[3*PST + t] = v23.y;
        }

        // ---- completion; last chunk of group runs epilogue ----------------
        __threadfence();
        __syncthreads();
        if (t == 0) {
            int old = atomicAdd(&g_gcnt[grp], 1);
            s_bc[3] = (old == SPLIT - 1);
        }
        __syncthreads();
        if (s_bc[3]) {
            __threadfence();
            float* pooled = s_dpf;           // [512]
            float* multi  = s_dpf + 512;     // [512]
            float* red8   = s_dpf + 1024;    // [512]
            const float* pg = g_part + (size_t)grp * SPLIT * H * PST;
            if (t < H) {
                float ss = 0.f;
                #pragma unroll
                for (int cc = 0; cc < SPLIT; cc++) ss += pg[(cc*H + t)*PST + F];
                s_sv[t] = 1.0f / ss;
            }
            __syncthreads();
            {
                int h = t >> 7, i = t & 127;
                float vv = 0.f;
                #pragma unroll
                for (int cc = 0; cc < SPLIT; cc++) vv += pg[(cc*H + h)*PST + i];
                pooled[t] = vv * s_sv[h];
            }
            __syncthreads();
            {
                int h = t >> 7, j = t & 127;
                const float* Wp = (h == 0) ? W1 : (h == 1) ? W2 : (h == 2) ? W3 : W4;
                float acc = 0.f;
                #pragma unroll 8
                for (int i = 0; i < F; i++)
                    acc = fmaf(pooled[h*F + i], Wp[i*F + j], acc);
                multi[t] = acc;
            }
            __syncthreads();
            {
                int oc = t & 63, seg = t >> 6;   // 8 segments of 64 k
                float acc = 0.f;
                #pragma unroll 8
                for (int kk = 0; kk < 64; kk++) {
                    int k = seg*64 + kk;
                    acc = fmaf(multi[k], Wo[k*64 + oc], acc);
                }
                red8[seg*64 + oc] = acc;
            }
            __syncthreads();
            if (t < 64) {
                float a = 0.f;
                #pragma unroll
                for (int sgg = 0; sgg < 8; sgg++) a += red8[sgg*64 + t];
                out[grp*64 + t] = (a > 0.f) ? a : expm1f(a);
            }
            __syncthreads();
        }

        cur = nx; nx = c2; buf = (buf == 2) ? 0 : buf + 1;
    }
}

// ---------------------------------------------------------------------------
extern "C" void kernel_launch(void* const* d_in, const int* in_sizes, int n_in,
                              void* d_out, int out_size) {
    const float* feat = (const float*)d_in[0];
    const float* W1   = (const float*)d_in[1];
    const float* a1   = (const float*)d_in[2];
    const float* W2   = (const float*)d_in[3];
    const float* a2   = (const float*)d_in[4];
    const float* W3   = (const float*)d_in[5];
    const float* a3   = (const float*)d_in[6];
    const float* W4   = (const float*)d_in[7];
    const float* a4   = (const float*)d_in[8];
    const float* Wo   = (const float*)d_in[9];
    float* out = (float*)d_out;

    cudaFuncSetAttribute(k1_main, cudaFuncAttributeMaxDynamicSharedMemorySize, SMEM_SZ);
    k0_wa<<<H + 1, 256>>>(W1, a1, W2, a2, W3, a3, W4, a4);
    k1_main<<<GRID1, TB, SMEM_SZ>>>(feat, W1, W2, W3, W4, Wo, out);
}

// round 15
// speedup vs baseline: 1.7584x; 1.2682x over previous
#include <cuda_runtime.h>

#define NG     64
#define NN     2048
#define F      128
#define H      4
#define UROWS  256              // rows per work unit
#define NUNIT  (NG*NN/UROWS)    // 512 units
#define UPG    (NN/UROWS)       // 8 units per group
#define TB     256
#define PSTU   528              // per-unit partial: 4 heads x 132 (v[128], s at [128])
#define GRID1  296              // 148 SM x 2 CTA persistent

__device__ float g_wa[H*F];
__device__ float g_part[NUNIT*PSTU];
__device__ int   g_work;
__device__ int   g_gcnt[NG];

// ---------------------------------------------------------------------------
// k0: wa per head (blocks 0..3) + counter reset (block 4)
// ---------------------------------------------------------------------------
__global__ void __launch_bounds__(256) k0_wa(
        const float* __restrict__ W1, const float* __restrict__ a1,
        const float* __restrict__ W2, const float* __restrict__ a2,
        const float* __restrict__ W3, const float* __restrict__ a3,
        const float* __restrict__ W4, const float* __restrict__ a4) {
    const int bid = blockIdx.x, t = threadIdx.x;
    if (bid == H) {
        if (t < NG) g_gcnt[t] = 0;
        if (t == NG) g_work = 0;
        return;
    }
    const float* W = (bid == 0) ? W1 : (bid == 1) ? W2 : (bid == 2) ? W3 : W4;
    const float* A = (bid == 0) ? a1 : (bid == 1) ? a2 : (bid == 2) ? a3 : a4;
    const int lane = t & 31, w = t >> 5;
    float4 av = *reinterpret_cast<const float4*>(A + lane*4);
    #pragma unroll
    for (int o = 0; o < 16; o++) {
        int i = w*16 + o;
        float4 wv = *reinterpret_cast<const float4*>(W + i*F + lane*4);
        float d = wv.x*av.x + wv.y*av.y + wv.z*av.z + wv.w*av.w;
        #pragma unroll
        for (int off = 16; off; off >>= 1)
            d += __shfl_xor_sync(0xffffffffu, d, off);
        if (lane == 0) g_wa[bid*F + i] = d;
    }
}

// ---------------------------------------------------------------------------
// k1: persistent streaming kernel. Octet-per-row, registers only, no staging.
// ---------------------------------------------------------------------------
__global__ void __launch_bounds__(TB) k1_main(
        const float* __restrict__ feat,
        const float* __restrict__ W1, const float* __restrict__ W2,
        const float* __restrict__ W3, const float* __restrict__ W4,
        const float* __restrict__ Wo, float* __restrict__ out) {
    __shared__ float s_wa[H*F];          // 2KB
    __shared__ float v_sm[8][H*F];       // 16KB  [warp][h*128+c]  (epilogue scratch too)
    __shared__ float s_sm[8][H];
    __shared__ float s_sv[H];
    __shared__ int   sbc[2];

    const int t = threadIdx.x, lane = t & 31, w = t >> 5;
    const int rq = lane >> 3;            // row-in-quad (0..3)
    const int cq = lane & 7;             // col-octant (0..7): cols cq*16..cq*16+15

    s_wa[t] = g_wa[t];
    s_wa[t + 256] = g_wa[t + 256];

    for (;;) {
        if (t == 0) sbc[0] = atomicAdd(&g_work, 1);
        __syncthreads();                  // also covers s_wa on first iter, v_sm reuse later
        const int u = sbc[0];
        if (u >= NUNIT) break;

        // warp w handles rows [u*256 + w*32, +32)
        const float* base = feat + (size_t)u * UROWS * F + (size_t)w * 32 * F
                            + (size_t)rq * F + (size_t)cq * 16;

        float  s[H]    = {0.f, 0.f, 0.f, 0.f};
        float4 v[H][4] = {};

        #pragma unroll
        for (int j = 0; j < 8; j++) {     // 8 quads of 4 rows
            const float* rp = base + (size_t)j * 4 * F;
            float4 x0 = *reinterpret_cast<const float4*>(rp + 0);
            float4 x1 = *reinterpret_cast<const float4*>(rp + 4);
            float4 x2 = *reinterpret_cast<const float4*>(rp + 8);
            float4 x3 = *reinterpret_cast<const float4*>(rp + 12);

            float d[H];
            #pragma unroll
            for (int h = 0; h < H; h++) {
                const float* wp = s_wa + h*F + cq*16;
                float4 w0 = *reinterpret_cast<const float4*>(wp + 0);
                float4 w1 = *reinterpret_cast<const float4*>(wp + 4);
                float4 w2 = *reinterpret_cast<const float4*>(wp + 8);
                float4 w3 = *reinterpret_cast<const float4*>(wp + 12);
                d[h] = x0.x*w0.x + x0.y*w0.y + x0.z*w0.z + x0.w*w0.w
                     + x1.x*w1.x + x1.y*w1.y + x1.z*w1.z + x1.w*w1.w
                     + x2.x*w2.x + x2.y*w2.y + x2.z*w2.z + x2.w*w2.w
                     + x3.x*w3.x + x3.y*w3.y + x3.z*w3.z + x3.w*w3.w;
            }
            // reduce across the 8-lane octet (xor 4,2,1) -> full row dot
            #pragma unroll
            for (int off = 4; off; off >>= 1) {
                #pragma unroll
                for (int h = 0; h < H; h++)
                    d[h] += __shfl_xor_sync(0xffffffffu, d[h], off);
            }
            #pragma unroll
            for (int h = 0; h < H; h++) {
                float p = __expf(d[h]);   // no max-shift: logits bounded (~|16|)
                s[h] += p;
                v[h][0].x += p*x0.x; v[h][0].y += p*x0.y; v[h][0].z += p*x0.z; v[h][0].w += p*x0.w;
                v[h][1].x += p*x1.x; v[h][1].y += p*x1.y; v[h][1].z += p*x1.z; v[h][1].w += p*x1.w;
                v[h][2].x += p*x2.x; v[h][2].y += p*x2.y; v[h][2].z += p*x2.z; v[h][2].w += p*x2.w;
                v[h][3].x += p*x3.x; v[h][3].y += p*x3.y; v[h][3].z += p*x3.z; v[h][3].w += p*x3.w;
            }
        }

        // cross-rq combine: xor 8,16 flips the rq bits -> sums the 4 row groups.
        // (cq duplication of s lives in bits 0-2 and is never summed: no /8.)
        #pragma unroll
        for (int h = 0; h < H; h++) {
            #pragma unroll
            for (int k = 0; k < 4; k++) {
                v[h][k].x += __shfl_xor_sync(0xffffffffu, v[h][k].x, 8);
                v[h][k].y += __shfl_xor_sync(0xffffffffu, v[h][k].y, 8);
                v[h][k].z += __shfl_xor_sync(0xffffffffu, v[h][k].z, 8);
                v[h][k].w += __shfl_xor_sync(0xffffffffu, v[h][k].w, 8);
                v[h][k].x += __shfl_xor_sync(0xffffffffu, v[h][k].x, 16);
                v[h][k].y += __shfl_xor_sync(0xffffffffu, v[h][k].y, 16);
                v[h][k].z += __shfl_xor_sync(0xffffffffu, v[h][k].z, 16);
                v[h][k].w += __shfl_xor_sync(0xffffffffu, v[h][k].w, 16);
            }
            s[h] += __shfl_xor_sync(0xffffffffu, s[h], 8);
            s[h] += __shfl_xor_sync(0xffffffffu, s[h], 16);
        }

        if (lane < 8) {
            #pragma unroll
            for (int h = 0; h < H; h++)
                #pragma unroll
                for (int k = 0; k < 4; k++)
                    *reinterpret_cast<float4*>(&v_sm[w][h*F + lane*16 + k*4]) = v[h][k];
        }
        if (lane == 0)
            #pragma unroll
            for (int h = 0; h < H; h++) s_sm[w][h] = s[h];
        __syncthreads();

        // CTA combine over 8 warps -> unit partial
        float* pb = g_part + (size_t)u * PSTU;
        #pragma unroll
        for (int rep = 0; rep < 2; rep++) {
            int o = t + rep*256;          // o in [0,512): h=o>>7, c=o&127
            float acc = 0.f;
            #pragma unroll
            for (int ww = 0; ww < 8; ww++) acc += v_sm[ww][o];
            pb[(o >> 7)*132 + (o & 127)] = acc;
        }
        if (t < H) {
            float ss = 0.f;
            #pragma unroll
            for (int ww = 0; ww < 8; ww++) ss += s_sm[ww][t];
            pb[t*132 + 128] = ss;
        }

        __threadfence();
        __syncthreads();                  // v_sm reads done (epilogue reuses it)
        if (t == 0) {
            int old = atomicAdd(&g_gcnt[u >> 3], 1);
            sbc[1] = (old == UPG - 1);
        }
        __syncthreads();
        if (sbc[1]) {
            __threadfence();
            const int grp = u >> 3;
            float* pooled = &v_sm[0][0];          // [512]
            float* multi  = &v_sm[1][0];          // [512]
            float* red4   = &v_sm[2][0];          // [256]
            const float* pg = g_part + (size_t)grp * UPG * PSTU;
            if (t < H) {
                float ss = 0.f;
                #pragma unroll
                for (int c = 0; c < UPG; c++) ss += pg[c*PSTU + t*132 + 128];
                s_sv[t] = 1.0f / ss;
            }
            __syncthreads();
            #pragma unroll
            for (int rep = 0; rep < 2; rep++) {
                int o = t + rep*256, h = o >> 7, i = o & 127;
                float vv = 0.f;
                #pragma unroll
                for (int c = 0; c < UPG; c++) vv += pg[c*PSTU + h*132 + i];
                pooled[o] = vv * s_sv[h];
            }
            __syncthreads();
            #pragma unroll
            for (int rep = 0; rep < 2; rep++) {
                int o = t + rep*256, h = o >> 7, j = o & 127;
                const float* Wp = (h == 0) ? W1 : (h == 1) ? W2 : (h == 2) ? W3 : W4;
                float acc = 0.f;
                #pragma unroll 8
                for (int i = 0; i < F; i++)
                    acc = fmaf(pooled[h*F + i], Wp[i*F + j], acc);
                multi[o] = acc;
            }
            __syncthreads();
            {
                int oc = t & 63, seg = t >> 6;    // 4 segments of 128 k
                float acc = 0.f;
                #pragma unroll 8
                for (int kk = 0; kk < 128; kk++) {
                    int k = seg*128 + kk;
                    acc = fmaf(multi[k], Wo[k*64 + oc], acc);
                }
                red4[seg*64 + oc] = acc;
            }
            __syncthreads();
            if (t < 64) {
                float a = red4[t] + red4[64 + t] + red4[128 + t] + red4[192 + t];
                out[grp*64 + t] = (a > 0.f) ? a : expm1f(a);
            }
            __syncthreads();              // epilogue scratch safe before next unit
        }
    }
}

// ---------------------------------------------------------------------------
extern "C" void kernel_launch(void* const* d_in, const int* in_sizes, int n_in,
                              void* d_out, int out_size) {
    const float* feat = (const float*)d_in[0];
    const float* W1   = (const float*)d_in[1];
    const float* a1   = (const float*)d_in[2];
    const float* W2   = (const float*)d_in[3];
    const float* a2   = (const float*)d_in[4];
    const float* W3   = (const float*)d_in[5];
    const float* a3   = (const float*)d_in[6];
    const float* W4   = (const float*)d_in[7];
    const float* a4   = (const float*)d_in[8];
    const float* Wo   = (const float*)d_in[9];
    float* out = (float*)d_out;

    k0_wa<<<H + 1, 256>>>(W1, a1, W2, a2, W3, a3, W4, a4);
    k1_main<<<GRID1, TB>>>(feat, W1, W2, W3, W4, Wo, out);
}

// round 17
// speedup vs baseline: 2.1558x; 1.2260x over previous
#include <cuda_runtime.h>

#define NG     64
#define NN     2048
#define F      128
#define H      4
#define UROWS  256              // rows per work unit
#define NUNIT  (NG*NN/UROWS)    // 512 units
#define UPG    (NN/UROWS)       // 8 units per group
#define TB     256
#define PSTU   528              // per-unit partial: 4 heads x 132
#define GRID1  296              // 148 SM x 2 CTA persistent

typedef unsigned long long u64;

__device__ float g_wa[H*F];
__device__ float g_part[NUNIT*PSTU];
__device__ int   g_work;
__device__ int   g_gcnt[NG];

__device__ __forceinline__ u64 ffma2(u64 a, u64 b, u64 c) {
    u64 d; asm("fma.rn.f32x2 %0,%1,%2,%3;" : "=l"(d) : "l"(a), "l"(b), "l"(c)); return d;
}
__device__ __forceinline__ u64 addf2(u64 a, u64 b) {
    u64 d; asm("add.rn.f32x2 %0,%1,%2;" : "=l"(d) : "l"(a), "l"(b)); return d;
}
__device__ __forceinline__ u64 dup2(float x) {
    u64 d; asm("mov.b64 %0,{%1,%1};" : "=l"(d) : "f"(x)); return d;
}
__device__ __forceinline__ float2 u2f(u64 v) {
    float2 r; asm("mov.b64 {%0,%1},%2;" : "=f"(r.x), "=f"(r.y) : "l"(v)); return r;
}

// ---------------------------------------------------------------------------
// k0: wa per head (blocks 0..3) + counter reset (block 4)
// ---------------------------------------------------------------------------
__global__ void __launch_bounds__(256) k0_wa(
        const float* __restrict__ W1, const float* __restrict__ a1,
        const float* __restrict__ W2, const float* __restrict__ a2,
        const float* __restrict__ W3, const float* __restrict__ a3,
        const float* __restrict__ W4, const float* __restrict__ a4) {
    const int bid = blockIdx.x, t = threadIdx.x;
    if (bid == H) {
        if (t < NG) g_gcnt[t] = 0;
        if (t == NG) g_work = 0;
        return;
    }
    const float* W = (bid == 0) ? W1 : (bid == 1) ? W2 : (bid == 2) ? W3 : W4;
    const float* A = (bid == 0) ? a1 : (bid == 1) ? a2 : (bid == 2) ? a3 : a4;
    const int lane = t & 31, w = t >> 5;
    float4 av = *reinterpret_cast<const float4*>(A + lane*4);
    #pragma unroll
    for (int o = 0; o < 16; o++) {
        int i = w*16 + o;
        float4 wv = *reinterpret_cast<const float4*>(W + i*F + lane*4);
        float d = wv.x*av.x + wv.y*av.y + wv.z*av.z + wv.w*av.w;
        #pragma unroll
        for (int off = 16; off; off >>= 1)
            d += __shfl_xor_sync(0xffffffffu, d, off);
        if (lane == 0) g_wa[bid*F + i] = d;
    }
}

// ---------------------------------------------------------------------------
// k1: persistent streaming. 16 lanes/row x 8 cols/lane, wa + v in registers.
// ---------------------------------------------------------------------------
__global__ void __launch_bounds__(TB, 2) k1_main(
        const float* __restrict__ feat,
        const float* __restrict__ W1, const float* __restrict__ W2,
        const float* __restrict__ W3, const float* __restrict__ W4,
        const float* __restrict__ Wo, float* __restrict__ out) {
    __shared__ float v_sm[8][H*F];       // 16KB  [warp][h*128+c]  (epilogue scratch too)
    __shared__ float s_sm[8][H];
    __shared__ float s_sv[H];
    __shared__ int   sbc[2];

    const int t = threadIdx.x, lane = t & 31, w = t >> 5;
    const int rb = lane >> 4;            // row-in-pair (0/1)
    const int cg = lane & 15;            // col group: cols cg*8 .. cg*8+7

    // wa in registers: 4 heads x 8 cols = 16 u64 (fixed col-set per lane)
    u64 wp[H][4];
    #pragma unroll
    for (int h = 0; h < H; h++) {
        const ulonglong2* gw = reinterpret_cast<const ulonglong2*>(g_wa + h*F + cg*8);
        ulonglong2 wA = gw[0], wB = gw[1];
        wp[h][0] = wA.x; wp[h][1] = wA.y; wp[h][2] = wB.x; wp[h][3] = wB.y;
    }

    for (;;) {
        if (t == 0) sbc[0] = atomicAdd(&g_work, 1);
        __syncthreads();                  // also protects v_sm reuse
        const int u = sbc[0];
        if (u >= NUNIT) break;

        // warp w: rows [u*256 + w*32, +32), two rows per iteration
        const float* base = feat + (size_t)u * UROWS * F + (size_t)w * 32 * F
                            + (size_t)rb * F + (size_t)cg * 8;

        float s[H]    = {0.f, 0.f, 0.f, 0.f};
        u64   v[H][4] = {};

        #pragma unroll
        for (int j = 0; j < 16; j++) {    // 16 row-pairs
            const ulonglong2* rp = reinterpret_cast<const ulonglong2*>(
                base + (size_t)j * 2 * F);
            ulonglong2 xA = rp[0], xB = rp[1];
            u64 xp0 = xA.x, xp1 = xA.y, xp2 = xB.x, xp3 = xB.y;

            float d[H];
            #pragma unroll
            for (int h = 0; h < H; h++) {
                u64 acc = ffma2(xp0, wp[h][0], 0ull);
                acc = ffma2(xp1, wp[h][1], acc);
                acc = ffma2(xp2, wp[h][2], acc);
                acc = ffma2(xp3, wp[h][3], acc);
                float2 f = u2f(acc);
                d[h] = f.x + f.y;
            }
            // reduce across the 16-lane row group (xor 1,2,4,8)
            #pragma unroll
            for (int off = 1; off <= 8; off <<= 1) {
                #pragma unroll
                for (int h = 0; h < H; h++)
                    d[h] += __shfl_xor_sync(0xffffffffu, d[h], off);
            }
            #pragma unroll
            for (int h = 0; h < H; h++) {
                float p = __expf(d[h]);   // logits bounded: no max shift needed
                s[h] += p;
                u64 p2 = dup2(p);
                v[h][0] = ffma2(p2, xp0, v[h][0]);
                v[h][1] = ffma2(p2, xp1, v[h][1]);
                v[h][2] = ffma2(p2, xp2, v[h][2]);
                v[h][3] = ffma2(p2, xp3, v[h][3]);
            }
        }

        // combine rb halves (xor 16). s duplication across cg is never summed.
        #pragma unroll
        for (int h = 0; h < H; h++) {
            #pragma unroll
            for (int k = 0; k < 4; k++)
                v[h][k] = addf2(v[h][k], __shfl_xor_sync(0xffffffffu, v[h][k], 16));
            s[h] += __shfl_xor_sync(0xffffffffu, s[h], 16);
        }

        if (rb == 0) {
            #pragma unroll
            for (int h = 0; h < H; h++) {
                ulonglong2* dst = reinterpret_cast<ulonglong2*>(&v_sm[w][h*F + cg*8]);
                ulonglong2 a, b;
                a.x = v[h][0]; a.y = v[h][1];
                b.x = v[h][2]; b.y = v[h][3];
                dst[0] = a; dst[1] = b;
            }
        }
        if (lane == 0)
            #pragma unroll
            for (int h = 0; h < H; h++) s_sm[w][h] = s[h];
        __syncthreads();

        // CTA combine over 8 warps -> unit partial
        float* pb = g_part + (size_t)u * PSTU;
        #pragma unroll
        for (int rep = 0; rep < 2; rep++) {
            int o = t + rep*256;          // h=o>>7, c=o&127
            float acc = 0.f;
            #pragma unroll
            for (int ww = 0; ww < 8; ww++) acc += v_sm[ww][o];
            pb[(o >> 7)*132 + (o & 127)] = acc;
        }
        if (t < H) {
            float ss = 0.f;
            #pragma unroll
            for (int ww = 0; ww < 8; ww++) ss += s_sm[ww][t];
            pb[t*132 + 128] = ss;
        }

        __threadfence();
        __syncthreads();                  // v_sm reads done (epilogue reuses it)
        if (t == 0) {
            int old = atomicAdd(&g_gcnt[u >> 3], 1);
            sbc[1] = (old == UPG - 1);
        }
        __syncthreads();
        if (sbc[1]) {
            __threadfence();
            const int grp = u >> 3;
            float* pooled = &v_sm[0][0];          // [512]
            float* multi  = &v_sm[1][0];          // [512]
            float* red4   = &v_sm[2][0];          // [256]
            const float* pg = g_part + (size_t)grp * UPG * PSTU;
            if (t < H) {
                float ss = 0.f;
                #pragma unroll
                for (int c = 0; c < UPG; c++) ss += pg[c*PSTU + t*132 + 128];
                s_sv[t] = 1.0f / ss;
            }
            __syncthreads();
            #pragma unroll
            for (int rep = 0; rep < 2; rep++) {
                int o = t + rep*256, h = o >> 7, i = o & 127;
                float vv = 0.f;
                #pragma unroll
                for (int c = 0; c < UPG; c++) vv += pg[c*PSTU + h*132 + i];
                pooled[o] = vv * s_sv[h];
            }
            __syncthreads();
            #pragma unroll
            for (int rep = 0; rep < 2; rep++) {
                int o = t + rep*256, h = o >> 7, j = o & 127;
                const float* Wp = (h == 0) ? W1 : (h == 1) ? W2 : (h == 2) ? W3 : W4;
                float acc = 0.f;
                #pragma unroll 8
                for (int i = 0; i < F; i++)
                    acc = fmaf(pooled[h*F + i], Wp[i*F + j], acc);
                multi[o] = acc;
            }
            __syncthreads();
            {
                int oc = t & 63, seg = t >> 6;    // 4 segments of 128 k
                float acc = 0.f;
                #pragma unroll 8
                for (int kk = 0; kk < 128; kk++) {
                    int k = seg*128 + kk;
                    acc = fmaf(multi[k], Wo[k*64 + oc], acc);
                }
                red4[seg*64 + oc] = acc;
            }
            __syncthreads();
            if (t < 64) {
                float a = red4[t] + red4[64 + t] + red4[128 + t] + red4[192 + t];
                out[grp*64 + t] = (a > 0.f) ? a : expm1f(a);
            }
            __syncthreads();              // epilogue scratch safe before next unit
        }
    }
}

// ---------------------------------------------------------------------------
extern "C" void kernel_launch(void* const* d_in, const int* in_sizes, int n_in,
                              void* d_out, int out_size) {
    const float* feat = (const float*)d_in[0];
    const float* W1   = (const float*)d_in[1];
    const float* a1   = (const float*)d_in[2];
    const float* W2   = (const float*)d_in[3];
    const float* a2   = (const float*)d_in[4];
    const float* W3   = (const float*)d_in[5];
    const float* a3   = (const float*)d_in[6];
    const float* W4   = (const float*)d_in[7];
    const float* a4   = (const float*)d_in[8];
    const float* Wo   = (const float*)d_in[9];
    float* out = (float*)d_out;

    k0_wa<<<H + 1, 256>>>(W1, a1, W2, a2, W3, a3, W4, a4);
    k1_main<<<GRID1, TB>>>(feat, W1, W2, W3, W4, Wo, out);
}